// round 13
// baseline (speedup 1.0000x reference)
#include <cuda_runtime.h>
#include <cstddef>

typedef unsigned long long ull;

// Problem constants (fixed by reference)
#define N_KC   200
#define N_MBON 20
#define N_FBN  60
#define N_DAN  20
#define N_REC  100
#define T_TOT  61
#define T_STEPS 60
#define NPAIR  4          // pair index p = lane + 32*i, valid p < 100; k = 2p, 2p+1
#define NTHREADS 320
#define WM_CHUNK 36       // Wm cols per thread-group (zero-padded)
#define WM_PAIRS 18
#define WM_Q     9

// smem layout (floats)
#define OFF_RK   0        // 12200 : r_kc slab NATURAL [k*61 + t]
#define OFF_R    12200    // 108   : current r, zero-padded to 108 (16B reads)
#define OFF_IB   12308    // 80    : I_kc partials (4 lanes x 20 rows)
#define OFF_WRP  12388    // 300   : Wr partials
#define OFF_RBK  12688    // 400   : rbk double buffer (2 x 200)
#define OFF_RBD  13088    // 20
#define OFF_BIAS 13108    // 100
#define OFF_WRO  13208    // 20
#define OFF_WEXT 13228    // 120
#define OFF_REXT 13348    // 122
#define SM_FLOATS 13470

#define FMA2(d,a,b,c) asm("fma.rn.f32x2 %0, %1, %2, %3;" : "=l"(d) : "l"(a), "l"(b), "l"(c))

// register-pair view: no pack/unpack instructions, just aliasing
union F2 {
    ull u;
    float2 f;
};

__global__ __launch_bounds__(NTHREADS, 2)
void cond_rnn_kernel(const float* __restrict__ r_kc,
                     const float* __restrict__ r_ext,
                     const float* __restrict__ timev,
                     const float* __restrict__ W0,
                     const float* __restrict__ wt0,
                     const float* __restrict__ W_recur,
                     const float* __restrict__ W_ext,
                     const float* __restrict__ W_readout,
                     const float* __restrict__ bias,
                     float* __restrict__ out,
                     int B)
{
    extern __shared__ float sm[];
    float* s_rk   = sm + OFF_RK;
    float* s_r    = sm + OFF_R;
    float* s_Ib   = sm + OFF_IB;
    float* s_wrp  = sm + OFF_WRP;
    float* s_rbk  = sm + OFF_RBK;   // two buffers of 200
    float* s_rbd  = sm + OFF_RBD;
    float* s_bias = sm + OFF_BIAS;
    float* s_wro  = sm + OFF_WRO;
    float* s_wext = sm + OFF_WEXT;
    float* s_rext = sm + OFF_REXT;

    const int b    = blockIdx.x;
    const int tid  = threadIdx.x;
    const int w    = tid >> 5;     // warp id 0..9
    const int lane = tid & 31;

    const float dt = timev[1] - timev[0];
    const float cW = dt * (1.0f / 5.0f);  // dt / TAU_W
    const float cR = dt;                  // dt / TAU_R

    // output section offsets
    const size_t WF   = (size_t)T_TOT * B * N_REC;
    const size_t WTF  = WF + (size_t)B * (N_MBON * N_KC);
    const size_t RO   = WTF + (size_t)B * (N_MBON * N_KC);

    // ---- stage r_kc[b] slab into smem (coalesced float4, natural layout) ----
    const float* rkb = r_kc + (size_t)b * (N_KC * T_TOT);
    {
        const float4* src = (const float4*)rkb;
        float4* dst = (float4*)s_rk;
        for (int i = tid; i < (N_KC * T_TOT) / 4; i += NTHREADS) dst[i] = src[i];
    }

    // ---- init small shared state ----
    if (tid < 100) {
        s_bias[tid] = bias[tid];
        float r0 = (tid < N_MBON) ? 0.0f : 0.1f;
        s_r[tid] = r0;
        out[(size_t)b * N_REC + tid] = r0;          // r_all[0]
    }
    if (tid >= 100 && tid < 108) s_r[tid] = 0.0f;   // zero pad for 16B Wr reads
    if (tid < 20)  { s_wro[tid] = W_readout[tid]; s_rbd[tid] = 0.1f; }
    if (tid < 120) s_wext[tid] = W_ext[tid];
    if (tid < 200) s_rbk[tid] = rkb[tid * T_TOT];   // rbk0 into buffer 0
    if (tid < 122) s_rext[tid] = r_ext[(size_t)b * (2 * T_TOT) + tid];
    if (tid == 0)  out[RO + b] = 0.0f;              // readout0 (MBON r is 0)

    // ---- plastic weights W / wt as register-pair unions: warp w owns rows (w, w+10) ----
    const int m1 = w;
    const int m2 = w + 10;
    F2 Wa2[NPAIR], Wb2[NPAIR], wta2[NPAIR], wtb2[NPAIR];
    {
        const float* Wg  = W0  + (size_t)b * (N_MBON * N_KC);
        const float* wtg = wt0 + (size_t)b * (N_MBON * N_KC);
        #pragma unroll
        for (int i = 0; i < NPAIR; i++) {
            int p = lane + 32 * i;
            bool ok = (p < 100);
            Wa2[i].u  = ok ? *(const ull*)(Wg  + m1 * N_KC + 2 * p) : 0ULL;
            Wb2[i].u  = ok ? *(const ull*)(Wg  + m2 * N_KC + 2 * p) : 0ULL;
            wta2[i].u = ok ? *(const ull*)(wtg + m1 * N_KC + 2 * p) : 0ULL;
            wtb2[i].u = ok ? *(const ull*)(wtg + m2 * N_KC + 2 * p) : 0ULL;
        }
    }

    // ---- W_recur (masked -> Wm) as register-pair unions: thread-group (jj, i0) ----
    F2 wm2[WM_PAIRS];
    const int jj = (tid < 300) ? (tid % 100) : 0;
    const int i0 = (tid < 300) ? (tid / 100) * WM_CHUNK : 0;
    #pragma unroll
    for (int c = 0; c < WM_PAIRS; c++) {
        int ia = i0 + 2 * c, ib = ia + 1;
        float va = 0.0f, vb = 0.0f;
        if (tid < 300 && ia < N_REC) {
            va = W_recur[jj * N_REC + ia];
            if (jj < N_MBON && ia >= N_REC - N_DAN) va = 0.0f;  // Wm mask
        }
        if (tid < 300 && ib < N_REC) {
            vb = W_recur[jj * N_REC + ib];
            if (jj < N_MBON && ib >= N_REC - N_DAN) vb = 0.0f;
        }
        wm2[c].f = make_float2(va, vb);
    }

    F2 cW2;  cW2.f  = make_float2(cW, cW);
    F2 n12;  n12.f  = make_float2(-1.0f, -1.0f);

    __syncthreads();

    float* out_r  = out + (size_t)B * N_REC + (size_t)b * N_REC;  // r_all[1]
    float* out_ro = out + RO + B + b;                              // readout[1]
    const size_t rstride = (size_t)B * N_REC;

    for (int t = 0; t < T_STEPS; t++) {
        const int cur = t & 1;
        const int nxt = cur ^ 1;
        const float* rk_t = s_rk + t;   // element k at rk_t[k * 61]

        // ================= P0 =================
        // rk pairs (8 scalar LDS into union halves) + I_kc row dots, packed
        F2 rk2[NPAIR];
        #pragma unroll
        for (int i = 0; i < NPAIR; i++) {
            int p = lane + 32 * i;
            if (p < 100) {
                rk2[i].f.x = rk_t[(2 * p)     * T_TOT];
                rk2[i].f.y = rk_t[(2 * p + 1) * T_TOT];
            } else {
                rk2[i].u = 0ULL;
            }
        }
        F2 a1, a2; a1.u = 0ULL; a2.u = 0ULL;
        #pragma unroll
        for (int i = 0; i < NPAIR; i++) {
            FMA2(a1.u, Wa2[i].u, rk2[i].u, a1.u);
            FMA2(a2.u, Wb2[i].u, rk2[i].u, a2.u);
        }
        float p1 = a1.f.x + a1.f.y;
        float p2 = a2.f.x + a2.f.y;
        // 3-level butterfly: lanes 0..3 hold partials over lanes == l mod 4
        #pragma unroll
        for (int o = 16; o >= 4; o >>= 1) {
            p1 += __shfl_xor_sync(0xFFFFFFFFu, p1, o);
            p2 += __shfl_xor_sync(0xFFFFFFFFu, p2, o);
        }
        if (lane < 4) {
            s_Ib[lane * 20 + m1] = p1;
            s_Ib[lane * 20 + m2] = p2;
        }

        // Wr partials: 9 x LDS.128 (as ull pairs) + 18 packed FMA2
        if (tid < 300) {
            const ulonglong2* rp = (const ulonglong2*)(s_r + i0);
            F2 acc0, acc1; acc0.u = 0ULL; acc1.u = 0ULL;
            #pragma unroll
            for (int c = 0; c < WM_Q; c++) {
                ulonglong2 rv = rp[c];
                FMA2(acc0.u, wm2[2 * c].u,     rv.x, acc0.u);
                FMA2(acc1.u, wm2[2 * c + 1].u, rv.y, acc1.u);
            }
            s_wrp[tid] = (acc0.f.x + acc0.f.y) + (acc1.f.x + acc1.f.y);
        }

        // rbk update on threads 120..319 (balances region-A warp loads)
        if (tid >= 120) {
            int k = tid - 120;                      // 0..199
            float rbk = s_rbk[cur * 200 + k];
            float rkt = rk_t[k * T_TOT];
            s_rbk[nxt * 200 + k] = fmaf(rkt - rbk, cW, rbk);
        }
        __syncthreads();

        // ================= P1 (I_fbn folded in) =================
        if (tid < N_REC) {
            float x = s_wrp[tid] + s_wrp[100 + tid] + s_wrp[200 + tid]
                    + s_bias[tid];
            if (tid < N_MBON) {
                x += (s_Ib[tid] + s_Ib[20 + tid]) + (s_Ib[40 + tid] + s_Ib[60 + tid]);
            } else if (tid < N_MBON + N_FBN) {
                int q = tid - N_MBON;
                float re0 = s_rext[t];
                float re1 = s_rext[T_TOT + t];
                x += fmaf(s_wext[2 * q], re0, s_wext[2 * q + 1] * re1);
            }
            float rold = s_r[tid];
            float rn = fmaf(fmaxf(x, 0.0f) - rold, cR, rold);
            s_r[tid] = rn;
            out_r[tid] = rn;
            if (tid >= N_REC - N_DAN) {
                int d = tid - (N_REC - N_DAN);
                float rbd = s_rbd[d];
                s_rbd[d] = fmaf(rn - rbd, cW, rbd);
            }
        }
        __syncthreads();

        // ====== P2 packed via unions (no trailing barrier; rbk double-buffered) ======
        {
            float rbd1d = s_rbd[m1] * dt,      rbd2d = s_rbd[m2] * dt;
            float rdn1d = -s_r[80 + m1] * dt,  rdn2d = -s_r[80 + m2] * dt;
            F2 rbd1p, rbd2p, rdn1p, rdn2p;
            rbd1p.f = make_float2(rbd1d, rbd1d);
            rbd2p.f = make_float2(rbd2d, rbd2d);
            rdn1p.f = make_float2(rdn1d, rdn1d);
            rdn2p.f = make_float2(rdn2d, rdn2d);
            const float* rbk_new = s_rbk + nxt * 200;
            #pragma unroll
            for (int i = 0; i < NPAIR; i++) {
                int p = lane + 32 * i;
                if (p < 100) {
                    F2 rbk2; rbk2.u = *(const ull*)(rbk_new + 2 * p);
                    F2 d1, d2;
                    // row m1: wt += rbd*dt*rk + (-rdan*dt)*rbk; W = clamp(lerp)
                    FMA2(wta2[i].u, rbd1p.u, rk2[i].u, wta2[i].u);
                    FMA2(wta2[i].u, rdn1p.u, rbk2.u,   wta2[i].u);
                    FMA2(d1.u, Wa2[i].u, n12.u, wta2[i].u);  // wta - Wa (one rounding)
                    FMA2(d1.u, d1.u, cW2.u, Wa2[i].u);       // Wa + (wta-Wa)*cW
                    Wa2[i].f.x = fminf(fmaxf(d1.f.x, 0.0f), 0.05f);
                    Wa2[i].f.y = fminf(fmaxf(d1.f.y, 0.0f), 0.05f);
                    // row m2
                    FMA2(wtb2[i].u, rbd2p.u, rk2[i].u, wtb2[i].u);
                    FMA2(wtb2[i].u, rdn2p.u, rbk2.u,   wtb2[i].u);
                    FMA2(d2.u, Wb2[i].u, n12.u, wtb2[i].u);
                    FMA2(d2.u, d2.u, cW2.u, Wb2[i].u);
                    Wb2[i].f.x = fminf(fmaxf(d2.f.x, 0.0f), 0.05f);
                    Wb2[i].f.y = fminf(fmaxf(d2.f.y, 0.0f), 0.05f);
                }
            }
        }

        // readout (warp 9, lightest-loaded; reads post-barrier s_r)
        if (w == 9) {
            float v = (lane < N_MBON) ? s_r[lane] * s_wro[lane] : 0.0f;
            #pragma unroll
            for (int o = 16; o > 0; o >>= 1)
                v += __shfl_xor_sync(0xFFFFFFFFu, v, o);
            if (lane == 0) *out_ro = v;
        }

        out_r  += rstride;
        out_ro += B;
        // no trailing barrier: next P0 writes s_Ib/s_wrp (readers in P1 are 1
        // barrier ahead; P2/readout don't touch them) and rbk buf[cur] (last
        // read by P0(t), 2 barriers back).
    }

    // ---- final W / wt (8B stores) ----
    {
        float* Wf  = out + WF  + (size_t)b * (N_MBON * N_KC);
        float* wtf = out + WTF + (size_t)b * (N_MBON * N_KC);
        #pragma unroll
        for (int i = 0; i < NPAIR; i++) {
            int p = lane + 32 * i;
            if (p < 100) {
                *(ull*)(Wf  + m1 * N_KC + 2 * p) = Wa2[i].u;
                *(ull*)(Wf  + m2 * N_KC + 2 * p) = Wb2[i].u;
                *(ull*)(wtf + m1 * N_KC + 2 * p) = wta2[i].u;
                *(ull*)(wtf + m2 * N_KC + 2 * p) = wtb2[i].u;
            }
        }
    }
}

extern "C" void kernel_launch(void* const* d_in, const int* in_sizes, int n_in,
                              void* d_out, int out_size) {
    const float* r_kc      = (const float*)d_in[0];
    const float* r_ext     = (const float*)d_in[1];
    const float* timev     = (const float*)d_in[2];
    const float* W0        = (const float*)d_in[3];
    const float* wt0       = (const float*)d_in[4];
    const float* W_recur   = (const float*)d_in[5];
    const float* W_ext     = (const float*)d_in[6];
    const float* W_readout = (const float*)d_in[7];
    const float* bias      = (const float*)d_in[8];
    float* out = (float*)d_out;

    int B = in_sizes[0] / (N_KC * T_TOT);

    static bool attr_set = false;
    if (!attr_set) {
        cudaFuncSetAttribute(cond_rnn_kernel,
                             cudaFuncAttributeMaxDynamicSharedMemorySize,
                             SM_FLOATS * sizeof(float));
        attr_set = true;
    }

    cond_rnn_kernel<<<B, NTHREADS, SM_FLOATS * sizeof(float)>>>(
        r_kc, r_ext, timev, W0, wt0, W_recur, W_ext, W_readout, bias, out, B);
}

// round 14
// speedup vs baseline: 1.0959x; 1.0959x over previous
#include <cuda_runtime.h>
#include <cstddef>

typedef unsigned long long ull;

// Problem constants (fixed by reference)
#define N_KC   200
#define N_MBON 20
#define N_FBN  60
#define N_DAN  20
#define N_REC  100
#define T_TOT  61
#define T_STEPS 60
#define KPT    7          // k = lane + 32*i, valid k < 200
#define NTHREADS 320
#define WM_CHUNK 36       // Wm cols per thread-group (zero-padded)
#define WM_PAIRS 18
#define WM_Q     9

// smem layout (floats)
#define OFF_RK   0        // 12200 : r_kc slab NATURAL [k*61 + t]
#define OFF_R    12200    // 108   : current r, zero-padded to 108 (16B reads)
#define OFF_IB   12308    // 80    : I_kc partials (4 lanes x 20 rows)
#define OFF_WRP  12388    // 300   : Wr partials
#define OFF_RBK  12688    // 400   : rbk double buffer (2 x 200)
#define OFF_RBD  13088    // 20
#define OFF_BIAS 13108    // 100
#define OFF_WRO  13208    // 20
#define OFF_WEXT 13228    // 120
#define OFF_REXT 13348    // 122
#define SM_FLOATS 13470

#define FMA2(d,a,b,c) asm("fma.rn.f32x2 %0, %1, %2, %3;" : "=l"(d) : "l"(a), "l"(b), "l"(c))

__device__ __forceinline__ ull pk2(float a, float b) {
    ull r;
    asm("mov.b64 %0, {%1, %2};" : "=l"(r)
        : "r"(__float_as_uint(a)), "r"(__float_as_uint(b)));
    return r;
}
__device__ __forceinline__ void upk2(ull v, float& a, float& b) {
    unsigned lo, hi;
    asm("mov.b64 {%0, %1}, %2;" : "=r"(lo), "=r"(hi) : "l"(v));
    a = __uint_as_float(lo); b = __uint_as_float(hi);
}

__global__ __launch_bounds__(NTHREADS, 2)
void cond_rnn_kernel(const float* __restrict__ r_kc,
                     const float* __restrict__ r_ext,
                     const float* __restrict__ timev,
                     const float* __restrict__ W0,
                     const float* __restrict__ wt0,
                     const float* __restrict__ W_recur,
                     const float* __restrict__ W_ext,
                     const float* __restrict__ W_readout,
                     const float* __restrict__ bias,
                     float* __restrict__ out,
                     int B)
{
    extern __shared__ float sm[];
    float* s_rk   = sm + OFF_RK;
    float* s_r    = sm + OFF_R;
    float* s_Ib   = sm + OFF_IB;
    float* s_wrp  = sm + OFF_WRP;
    float* s_rbk  = sm + OFF_RBK;   // two buffers of 200
    float* s_rbd  = sm + OFF_RBD;
    float* s_bias = sm + OFF_BIAS;
    float* s_wro  = sm + OFF_WRO;
    float* s_wext = sm + OFF_WEXT;
    float* s_rext = sm + OFF_REXT;

    const int b    = blockIdx.x;
    const int tid  = threadIdx.x;
    const int w    = tid >> 5;     // warp id 0..9
    const int lane = tid & 31;

    const float dt = timev[1] - timev[0];
    const float cW = dt * (1.0f / 5.0f);  // dt / TAU_W
    const float cR = dt;                  // dt / TAU_R

    // output section offsets
    const size_t WF   = (size_t)T_TOT * B * N_REC;
    const size_t WTF  = WF + (size_t)B * (N_MBON * N_KC);
    const size_t RO   = WTF + (size_t)B * (N_MBON * N_KC);

    // ---- stage r_kc[b] slab into smem (coalesced float4, natural layout) ----
    const float* rkb = r_kc + (size_t)b * (N_KC * T_TOT);
    {
        const float4* src = (const float4*)rkb;
        float4* dst = (float4*)s_rk;
        for (int i = tid; i < (N_KC * T_TOT) / 4; i += NTHREADS) dst[i] = src[i];
    }

    // ---- init small shared state ----
    if (tid < 100) {
        s_bias[tid] = bias[tid];
        float r0 = (tid < N_MBON) ? 0.0f : 0.1f;
        s_r[tid] = r0;
        out[(size_t)b * N_REC + tid] = r0;          // r_all[0]
    }
    if (tid >= 100 && tid < 108) s_r[tid] = 0.0f;   // zero pad for 16B Wr reads
    if (tid < 20)  { s_wro[tid] = W_readout[tid]; s_rbd[tid] = 0.1f; }
    if (tid < 120) s_wext[tid] = W_ext[tid];
    if (tid < 200) s_rbk[tid] = rkb[tid * T_TOT];   // rbk0 into buffer 0
    if (tid < 122) s_rext[tid] = r_ext[(size_t)b * (2 * T_TOT) + tid];
    if (tid == 0)  out[RO + b] = 0.0f;              // readout0 (MBON r is 0)

    // ---- plastic weights W / wt in SCALAR registers: warp w owns rows (w, w+10) ----
    const int m1 = w;
    const int m2 = w + 10;
    float Wa[KPT], Wb_[KPT], wta[KPT], wtb[KPT];
    {
        const float* Wg  = W0  + (size_t)b * (N_MBON * N_KC);
        const float* wtg = wt0 + (size_t)b * (N_MBON * N_KC);
        #pragma unroll
        for (int i = 0; i < KPT; i++) {
            int k = lane + 32 * i;
            bool ok = (k < N_KC);
            Wa[i]  = ok ? Wg [m1 * N_KC + k] : 0.0f;
            Wb_[i] = ok ? Wg [m2 * N_KC + k] : 0.0f;
            wta[i] = ok ? wtg[m1 * N_KC + k] : 0.0f;
            wtb[i] = ok ? wtg[m2 * N_KC + k] : 0.0f;
        }
    }

    // ---- W_recur (masked -> Wm) PACKED in registers (transient use only) ----
    ull wm2[WM_PAIRS];
    const int jj = (tid < 300) ? (tid % 100) : 0;
    const int i0 = (tid < 300) ? (tid / 100) * WM_CHUNK : 0;
    #pragma unroll
    for (int c = 0; c < WM_PAIRS; c++) {
        int ia = i0 + 2 * c, ib = ia + 1;
        float va = 0.0f, vb = 0.0f;
        if (tid < 300 && ia < N_REC) {
            va = W_recur[jj * N_REC + ia];
            if (jj < N_MBON && ia >= N_REC - N_DAN) va = 0.0f;  // Wm mask
        }
        if (tid < 300 && ib < N_REC) {
            vb = W_recur[jj * N_REC + ib];
            if (jj < N_MBON && ib >= N_REC - N_DAN) vb = 0.0f;
        }
        wm2[c] = pk2(va, vb);
    }

    __syncthreads();

    float* out_r  = out + (size_t)B * N_REC + (size_t)b * N_REC;  // r_all[1]
    float* out_ro = out + RO + B + b;                              // readout[1]
    const size_t rstride = (size_t)B * N_REC;

    for (int t = 0; t < T_STEPS; t++) {
        const int cur = t & 1;
        const int nxt = cur ^ 1;

        // ================= P0 =================
        // rk into regs + I_kc row dots (2 independent chains)
        float rk[KPT];
        #pragma unroll
        for (int i = 0; i < KPT; i++) {
            int k = lane + 32 * i;
            rk[i] = (k < N_KC) ? s_rk[k * T_TOT + t] : 0.0f;
        }
        float p1 = 0.0f, p2 = 0.0f;
        #pragma unroll
        for (int i = 0; i < KPT; i++) {
            p1 = fmaf(Wa[i],  rk[i], p1);
            p2 = fmaf(Wb_[i], rk[i], p2);
        }
        // fold-16 joint reduction: lanes 0-3 carry p1 partials, 16-19 carry p2
        {
            float q1 = p1 + __shfl_xor_sync(0xFFFFFFFFu, p1, 16);
            float q2 = p2 + __shfl_xor_sync(0xFFFFFFFFu, p2, 16);
            float v  = (lane & 16) ? q2 : q1;
            v += __shfl_xor_sync(0xFFFFFFFFu, v, 8);
            v += __shfl_xor_sync(0xFFFFFFFFu, v, 4);
            if ((lane & 12) == 0) {
                int row = (lane & 16) ? m2 : m1;
                s_Ib[(lane & 3) * 20 + row] = v;
            }
        }

        // Wr partials: 9 x LDS.128 (as ull pairs) + 18 packed FMA2
        if (tid < 300) {
            const ulonglong2* rp = (const ulonglong2*)(s_r + i0);
            ull acc0 = 0ULL, acc1 = 0ULL;
            #pragma unroll
            for (int c = 0; c < WM_Q; c++) {
                ulonglong2 rv = rp[c];
                FMA2(acc0, wm2[2 * c],     rv.x, acc0);
                FMA2(acc1, wm2[2 * c + 1], rv.y, acc1);
            }
            float f0, f1, f2, f3;
            upk2(acc0, f0, f1);
            upk2(acc1, f2, f3);
            s_wrp[tid] = (f0 + f1) + (f2 + f3);
        }

        // rbk update on threads 120..319 (off the I_kc+Wr-heavy warps 0..3)
        if (tid >= 120) {
            int k = tid - 120;                      // 0..199
            float rbk = s_rbk[cur * 200 + k];
            float rkt = s_rk[k * T_TOT + t];
            s_rbk[nxt * 200 + k] = fmaf(rkt - rbk, cW, rbk);
        }
        __syncthreads();

        // ================= P1 (I_fbn folded in) =================
        if (tid < N_REC) {
            float x = s_wrp[tid] + s_wrp[100 + tid] + s_wrp[200 + tid]
                    + s_bias[tid];
            if (tid < N_MBON) {
                x += (s_Ib[tid] + s_Ib[20 + tid]) + (s_Ib[40 + tid] + s_Ib[60 + tid]);
            } else if (tid < N_MBON + N_FBN) {
                int q = tid - N_MBON;
                float re0 = s_rext[t];
                float re1 = s_rext[T_TOT + t];
                x += fmaf(s_wext[2 * q], re0, s_wext[2 * q + 1] * re1);
            }
            float rold = s_r[tid];
            float rn = fmaf(fmaxf(x, 0.0f) - rold, cR, rold);
            s_r[tid] = rn;
            out_r[tid] = rn;
            if (tid >= N_REC - N_DAN) {
                int d = tid - (N_REC - N_DAN);
                float rbd = s_rbd[d];
                s_rbd[d] = fmaf(rn - rbd, cW, rbd);
            }
        }
        __syncthreads();

        // ================= P2 (no trailing barrier; rbk double-buffered) ====
        {
            float rbd1d = s_rbd[m1] * dt,      rbd2d = s_rbd[m2] * dt;
            float rdn1d = -s_r[80 + m1] * dt,  rdn2d = -s_r[80 + m2] * dt;
            const float* rbk_new = s_rbk + nxt * 200;
            #pragma unroll
            for (int i = 0; i < KPT; i++) {
                int k = lane + 32 * i;
                if (k < N_KC) {
                    float rbk = rbk_new[k];
                    wta[i] = fmaf(rbd1d, rk[i], wta[i]);
                    wta[i] = fmaf(rdn1d, rbk,   wta[i]);
                    Wa[i]  = fminf(fmaxf(fmaf(wta[i] - Wa[i], cW, Wa[i]), 0.0f), 0.05f);
                    wtb[i] = fmaf(rbd2d, rk[i], wtb[i]);
                    wtb[i] = fmaf(rdn2d, rbk,   wtb[i]);
                    Wb_[i] = fminf(fmaxf(fmaf(wtb[i] - Wb_[i], cW, Wb_[i]), 0.0f), 0.05f);
                }
            }
        }

        // readout (warp 9, lightest-loaded; reads post-barrier s_r)
        if (w == 9) {
            float v = (lane < N_MBON) ? s_r[lane] * s_wro[lane] : 0.0f;
            #pragma unroll
            for (int o = 16; o > 0; o >>= 1)
                v += __shfl_xor_sync(0xFFFFFFFFu, v, o);
            if (lane == 0) *out_ro = v;
        }

        out_r  += rstride;
        out_ro += B;
        // no trailing barrier: next P0 writes s_Ib/s_wrp (readers in P1 are 1
        // barrier ahead; P2/readout don't touch them) and rbk buf[cur] (last
        // read by P0(t), 2 barriers back).
    }

    // ---- final W / wt ----
    {
        float* Wf  = out + WF  + (size_t)b * (N_MBON * N_KC);
        float* wtf = out + WTF + (size_t)b * (N_MBON * N_KC);
        #pragma unroll
        for (int i = 0; i < KPT; i++) {
            int k = lane + 32 * i;
            if (k < N_KC) {
                Wf [m1 * N_KC + k] = Wa[i];
                Wf [m2 * N_KC + k] = Wb_[i];
                wtf[m1 * N_KC + k] = wta[i];
                wtf[m2 * N_KC + k] = wtb[i];
            }
        }
    }
}

extern "C" void kernel_launch(void* const* d_in, const int* in_sizes, int n_in,
                              void* d_out, int out_size) {
    const float* r_kc      = (const float*)d_in[0];
    const float* r_ext     = (const float*)d_in[1];
    const float* timev     = (const float*)d_in[2];
    const float* W0        = (const float*)d_in[3];
    const float* wt0       = (const float*)d_in[4];
    const float* W_recur   = (const float*)d_in[5];
    const float* W_ext     = (const float*)d_in[6];
    const float* W_readout = (const float*)d_in[7];
    const float* bias      = (const float*)d_in[8];
    float* out = (float*)d_out;

    int B = in_sizes[0] / (N_KC * T_TOT);

    static bool attr_set = false;
    if (!attr_set) {
        cudaFuncSetAttribute(cond_rnn_kernel,
                             cudaFuncAttributeMaxDynamicSharedMemorySize,
                             SM_FLOATS * sizeof(float));
        attr_set = true;
    }

    cond_rnn_kernel<<<B, NTHREADS, SM_FLOATS * sizeof(float)>>>(
        r_kc, r_ext, timev, W0, wt0, W_recur, W_ext, W_readout, bias, out, B);
}

// round 15
// speedup vs baseline: 1.2018x; 1.0967x over previous
#include <cuda_runtime.h>
#include <cstddef>

typedef unsigned long long ull;

// Problem constants (fixed by reference)
#define N_KC   200
#define N_MBON 20
#define N_FBN  60
#define N_DAN  20
#define N_REC  100
#define T_TOT  61
#define T_STEPS 60
#define KPT    7          // k = lane + 32*i, valid k < 200
#define NTHREADS 320
#define WM_CHUNK 36       // Wm cols per thread-group (zero-padded)
#define WM_PAIRS 18
#define WM_Q     9

// smem layout (floats)
#define OFF_RK   0        // 12200 : r_kc slab NATURAL [k*61 + t]
#define OFF_R    12200    // 108   : current r, zero-padded to 108 (16B reads)
#define OFF_IB   12308    // 80    : I_kc partials (4 lanes x 20 rows)
#define OFF_WRP  12388    // 300   : Wr partials
#define OFF_RBK  12688    // 400   : rbk double buffer (2 x 200)
#define OFF_RBD  13088    // 20
#define OFF_BIAS 13108    // 100
#define OFF_WRO  13208    // 20
#define OFF_WEXT 13228    // 120
#define OFF_REXT 13348    // 122
#define SM_FLOATS 13470

#define FMA2(d,a,b,c) asm("fma.rn.f32x2 %0, %1, %2, %3;" : "=l"(d) : "l"(a), "l"(b), "l"(c))

__device__ __forceinline__ ull pk2(float a, float b) {
    ull r;
    asm("mov.b64 %0, {%1, %2};" : "=l"(r)
        : "r"(__float_as_uint(a)), "r"(__float_as_uint(b)));
    return r;
}
__device__ __forceinline__ void upk2(ull v, float& a, float& b) {
    unsigned lo, hi;
    asm("mov.b64 {%0, %1}, %2;" : "=r"(lo), "=r"(hi) : "l"(v));
    a = __uint_as_float(lo); b = __uint_as_float(hi);
}

__global__ __launch_bounds__(NTHREADS, 2)
void cond_rnn_kernel(const float* __restrict__ r_kc,
                     const float* __restrict__ r_ext,
                     const float* __restrict__ timev,
                     const float* __restrict__ W0,
                     const float* __restrict__ wt0,
                     const float* __restrict__ W_recur,
                     const float* __restrict__ W_ext,
                     const float* __restrict__ W_readout,
                     const float* __restrict__ bias,
                     float* __restrict__ out,
                     int B)
{
    extern __shared__ float sm[];
    float* s_rk   = sm + OFF_RK;
    float* s_r    = sm + OFF_R;
    float* s_Ib   = sm + OFF_IB;
    float* s_wrp  = sm + OFF_WRP;
    float* s_rbk  = sm + OFF_RBK;   // two buffers of 200
    float* s_rbd  = sm + OFF_RBD;
    float* s_bias = sm + OFF_BIAS;
    float* s_wro  = sm + OFF_WRO;
    float* s_wext = sm + OFF_WEXT;
    float* s_rext = sm + OFF_REXT;

    const int b    = blockIdx.x;
    const int tid  = threadIdx.x;
    const int w    = tid >> 5;     // warp id 0..9
    const int lane = tid & 31;

    const float dt = timev[1] - timev[0];
    const float cW = dt * (1.0f / 5.0f);  // dt / TAU_W
    const float cR = dt;                  // dt / TAU_R

    // output section offsets
    const size_t WF   = (size_t)T_TOT * B * N_REC;
    const size_t WTF  = WF + (size_t)B * (N_MBON * N_KC);
    const size_t RO   = WTF + (size_t)B * (N_MBON * N_KC);

    // ---- stage r_kc[b] slab into smem (coalesced float4, natural layout) ----
    const float* rkb = r_kc + (size_t)b * (N_KC * T_TOT);
    {
        const float4* src = (const float4*)rkb;
        float4* dst = (float4*)s_rk;
        for (int i = tid; i < (N_KC * T_TOT) / 4; i += NTHREADS) dst[i] = src[i];
    }

    // ---- init small shared state ----
    if (tid < 100) {
        s_bias[tid] = bias[tid];
        float r0 = (tid < N_MBON) ? 0.0f : 0.1f;
        s_r[tid] = r0;
        out[(size_t)b * N_REC + tid] = r0;          // r_all[0]
    }
    if (tid >= 100 && tid < 108) s_r[tid] = 0.0f;   // zero pad for 16B Wr reads
    if (tid < 20)  { s_wro[tid] = W_readout[tid]; s_rbd[tid] = 0.1f; }
    if (tid < 120) s_wext[tid] = W_ext[tid];
    if (tid < 200) s_rbk[tid] = rkb[tid * T_TOT];   // rbk0 into buffer 0
    if (tid < 122) s_rext[tid] = r_ext[(size_t)b * (2 * T_TOT) + tid];
    if (tid == 0)  out[RO + b] = 0.0f;              // readout0 (MBON r is 0)

    // ---- plastic weights W / wt in SCALAR registers: warp w owns rows (w, w+10) ----
    const int m1 = w;
    const int m2 = w + 10;
    float Wa[KPT], Wb_[KPT], wta[KPT], wtb[KPT];
    {
        const float* Wg  = W0  + (size_t)b * (N_MBON * N_KC);
        const float* wtg = wt0 + (size_t)b * (N_MBON * N_KC);
        #pragma unroll
        for (int i = 0; i < KPT; i++) {
            int k = lane + 32 * i;
            bool ok = (k < N_KC);
            Wa[i]  = ok ? Wg [m1 * N_KC + k] : 0.0f;
            Wb_[i] = ok ? Wg [m2 * N_KC + k] : 0.0f;
            wta[i] = ok ? wtg[m1 * N_KC + k] : 0.0f;
            wtb[i] = ok ? wtg[m2 * N_KC + k] : 0.0f;
        }
    }

    // ---- W_recur (masked -> Wm) PACKED in registers (transient use only) ----
    ull wm2[WM_PAIRS];
    const int jj = (tid < 300) ? (tid % 100) : 0;
    const int i0 = (tid < 300) ? (tid / 100) * WM_CHUNK : 0;
    #pragma unroll
    for (int c = 0; c < WM_PAIRS; c++) {
        int ia = i0 + 2 * c, ib = ia + 1;
        float va = 0.0f, vb = 0.0f;
        if (tid < 300 && ia < N_REC) {
            va = W_recur[jj * N_REC + ia];
            if (jj < N_MBON && ia >= N_REC - N_DAN) va = 0.0f;  // Wm mask
        }
        if (tid < 300 && ib < N_REC) {
            vb = W_recur[jj * N_REC + ib];
            if (jj < N_MBON && ib >= N_REC - N_DAN) vb = 0.0f;
        }
        wm2[c] = pk2(va, vb);
    }

    __syncthreads();

    float* out_r  = out + (size_t)B * N_REC + (size_t)b * N_REC;  // r_all[1]
    const size_t rstride = (size_t)B * N_REC;

    for (int t = 0; t < T_STEPS; t++) {
        const int cur = t & 1;
        const int nxt = cur ^ 1;

        // ================= P0 =================
        // rk into regs + I_kc row dots (2 independent chains)
        float rk[KPT];
        #pragma unroll
        for (int i = 0; i < KPT; i++) {
            int k = lane + 32 * i;
            rk[i] = (k < N_KC) ? s_rk[k * T_TOT + t] : 0.0f;
        }
        float p1 = 0.0f, p2 = 0.0f;
        #pragma unroll
        for (int i = 0; i < KPT; i++) {
            p1 = fmaf(Wa[i],  rk[i], p1);
            p2 = fmaf(Wb_[i], rk[i], p2);
        }
        // 3-level butterfly: lanes 0..3 hold partials over lanes == l mod 4
        #pragma unroll
        for (int o = 16; o >= 4; o >>= 1) {
            p1 += __shfl_xor_sync(0xFFFFFFFFu, p1, o);
            p2 += __shfl_xor_sync(0xFFFFFFFFu, p2, o);
        }
        if (lane < 4) {
            s_Ib[lane * 20 + m1] = p1;
            s_Ib[lane * 20 + m2] = p2;
        }

        // Wr partials: 9 x LDS.128 (as ull pairs) + 18 packed FMA2
        if (tid < 300) {
            const ulonglong2* rp = (const ulonglong2*)(s_r + i0);
            ull acc0 = 0ULL, acc1 = 0ULL;
            #pragma unroll
            for (int c = 0; c < WM_Q; c++) {
                ulonglong2 rv = rp[c];
                FMA2(acc0, wm2[2 * c],     rv.x, acc0);
                FMA2(acc1, wm2[2 * c + 1], rv.y, acc1);
            }
            float f0, f1, f2, f3;
            upk2(acc0, f0, f1);
            upk2(acc1, f2, f3);
            s_wrp[tid] = (f0 + f1) + (f2 + f3);
        }

        // rbk update: read buf[cur], write buf[nxt]  (same mapping as R11 best)
        if (tid < N_KC) {
            float rbk = s_rbk[cur * 200 + tid];
            float rkt = s_rk[tid * T_TOT + t];
            s_rbk[nxt * 200 + tid] = fmaf(rkt - rbk, cW, rbk);
        }

        // readout of r(t) (warp 9, its light phase; s_r holds r(t) here,
        // valid since P1(t-1) one barrier back; t=0 handled at init)
        if (w == 9 && t > 0) {
            float v = (lane < N_MBON) ? s_r[lane] * s_wro[lane] : 0.0f;
            #pragma unroll
            for (int o = 16; o > 0; o >>= 1)
                v += __shfl_xor_sync(0xFFFFFFFFu, v, o);
            if (lane == 0) out[RO + (size_t)t * B + b] = v;
        }
        __syncthreads();

        // ================= P1 (I_fbn folded in) =================
        if (tid < N_REC) {
            float x = s_wrp[tid] + s_wrp[100 + tid] + s_wrp[200 + tid]
                    + s_bias[tid];
            if (tid < N_MBON) {
                x += (s_Ib[tid] + s_Ib[20 + tid]) + (s_Ib[40 + tid] + s_Ib[60 + tid]);
            } else if (tid < N_MBON + N_FBN) {
                int q = tid - N_MBON;
                float re0 = s_rext[t];
                float re1 = s_rext[T_TOT + t];
                x += fmaf(s_wext[2 * q], re0, s_wext[2 * q + 1] * re1);
            }
            float rold = s_r[tid];
            float rn = fmaf(fmaxf(x, 0.0f) - rold, cR, rold);
            s_r[tid] = rn;
            out_r[tid] = rn;
            if (tid >= N_REC - N_DAN) {
                int d = tid - (N_REC - N_DAN);
                float rbd = s_rbd[d];
                s_rbd[d] = fmaf(rn - rbd, cW, rbd);
            }
        }
        __syncthreads();

        // ================= P2 (no trailing barrier; rbk double-buffered) ====
        {
            float rbd1d = s_rbd[m1] * dt,      rbd2d = s_rbd[m2] * dt;
            float rdn1d = -s_r[80 + m1] * dt,  rdn2d = -s_r[80 + m2] * dt;
            const float* rbk_new = s_rbk + nxt * 200;
            #pragma unroll
            for (int i = 0; i < KPT; i++) {
                int k = lane + 32 * i;
                if (k < N_KC) {
                    float rbk = rbk_new[k];
                    wta[i] = fmaf(rbd1d, rk[i], wta[i]);
                    wta[i] = fmaf(rdn1d, rbk,   wta[i]);
                    Wa[i]  = fminf(fmaxf(fmaf(wta[i] - Wa[i], cW, Wa[i]), 0.0f), 0.05f);
                    wtb[i] = fmaf(rbd2d, rk[i], wtb[i]);
                    wtb[i] = fmaf(rdn2d, rbk,   wtb[i]);
                    Wb_[i] = fminf(fmaxf(fmaf(wtb[i] - Wb_[i], cW, Wb_[i]), 0.0f), 0.05f);
                }
            }
        }

        out_r += rstride;
        // no trailing barrier: next P0 writes s_Ib/s_wrp (readers in P1 are 1
        // barrier ahead; P2 doesn't touch them) and rbk buf[cur] (last read
        // by P0(t), 2 barriers back). Next P0's readout reads s_r, written
        // in P1 one barrier back — safe.
    }

    // ---- tail: readout of r(60) (s_r final, written in P1(59)) ----
    if (w == 9) {
        float v = (lane < N_MBON) ? s_r[lane] * s_wro[lane] : 0.0f;
        #pragma unroll
        for (int o = 16; o > 0; o >>= 1)
            v += __shfl_xor_sync(0xFFFFFFFFu, v, o);
        if (lane == 0) out[RO + (size_t)T_STEPS * B + b] = v;
    }

    // ---- final W / wt ----
    {
        float* Wf  = out + WF  + (size_t)b * (N_MBON * N_KC);
        float* wtf = out + WTF + (size_t)b * (N_MBON * N_KC);
        #pragma unroll
        for (int i = 0; i < KPT; i++) {
            int k = lane + 32 * i;
            if (k < N_KC) {
                Wf [m1 * N_KC + k] = Wa[i];
                Wf [m2 * N_KC + k] = Wb_[i];
                wtf[m1 * N_KC + k] = wta[i];
                wtf[m2 * N_KC + k] = wtb[i];
            }
        }
    }
}

extern "C" void kernel_launch(void* const* d_in, const int* in_sizes, int n_in,
                              void* d_out, int out_size) {
    const float* r_kc      = (const float*)d_in[0];
    const float* r_ext     = (const float*)d_in[1];
    const float* timev     = (const float*)d_in[2];
    const float* W0        = (const float*)d_in[3];
    const float* wt0       = (const float*)d_in[4];
    const float* W_recur   = (const float*)d_in[5];
    const float* W_ext     = (const float*)d_in[6];
    const float* W_readout = (const float*)d_in[7];
    const float* bias      = (const float*)d_in[8];
    float* out = (float*)d_out;

    int B = in_sizes[0] / (N_KC * T_TOT);

    static bool attr_set = false;
    if (!attr_set) {
        cudaFuncSetAttribute(cond_rnn_kernel,
                             cudaFuncAttributeMaxDynamicSharedMemorySize,
                             SM_FLOATS * sizeof(float));
        attr_set = true;
    }

    cond_rnn_kernel<<<B, NTHREADS, SM_FLOATS * sizeof(float)>>>(
        r_kc, r_ext, timev, W0, wt0, W_recur, W_ext, W_readout, bias, out, B);
}